// round 9
// baseline (speedup 1.0000x reference)
#include <cuda_runtime.h>
#include <cuda_bf16.h>
#include <math.h>

#define SIZE   512
#define N_PHOS 256
#define H      10
#define THRESH 0.05f

#define MAX_OH 52        // disk span (<=31) + 2H + 1
#define MAX_TW 73        // MAX_OH + 2H (+1 pad)

#define NBLOCKS  N_PHOS          // 256 blocks, one per phosphene
#define NTHREADS 256
#define PX_PER_BLOCK ((SIZE * SIZE) / NBLOCKS)   // 1024

__device__ int      g_max_bits = 0;   // clamped-image max as float bits (>=0)
__device__ unsigned g_bar_count = 0;  // barrier arrival counter (self-restoring)
__device__ unsigned g_bar_gen   = 0;  // barrier generation (monotonic)

static __device__ __forceinline__ int refl(int i) {
    if (i < 0)        i = -i;
    if (i > SIZE - 1) i = 2 * (SIZE - 1) - i;
    return i;
}

// Sense-reversing software grid barrier. Safe: all NBLOCKS are co-resident
// (see launch bounds / smem analysis). State self-restores each use, so the
// kernel is graph-replay deterministic.
static __device__ __forceinline__ void grid_barrier() {
    __syncthreads();
    if (threadIdx.x == 0) {
        unsigned my_gen = *((volatile unsigned*)&g_bar_gen);
        __threadfence();                       // make this block's writes visible
        unsigned arrived = atomicAdd(&g_bar_count, 1u);
        if (arrived == NBLOCKS - 1) {
            atomicExch(&g_bar_count, 0u);
            __threadfence();
            atomicExch(&g_bar_gen, my_gen + 1u);
        } else {
            while (*((volatile unsigned*)&g_bar_gen) == my_gen) { __nanosleep(64); }
        }
        __threadfence();                       // acquire: see other blocks' writes
    }
    __syncthreads();
}

__global__ __launch_bounds__(NTHREADS, 2) void k_fused(
    const float* __restrict__ phoscoding,
    const float* __restrict__ grid,
    float* __restrict__ img)
{
    const int p   = blockIdx.x;
    const int tid = threadIdx.x;

    __shared__ float w[2 * H + 1];
    __shared__ float s_wsum;
    __shared__ float t[MAX_OH][MAX_TW];

    // ---------------- Phase A: zero image, reset max ----------------
    {
        int base = p * PX_PER_BLOCK + tid * 4;     // exactly one float4 per thread
        *reinterpret_cast<float4*>(img + base) = make_float4(0.f, 0.f, 0.f, 0.f);
        if (p == 0 && tid == 0) g_max_bits = 0;
    }

    // ---- overlap: build blur weights for this block's phosphene ----
    const float bright = phoscoding[p];
    const float x = grid[3 * p + 0];
    const float y = grid[3 * p + 1];
    const float r = grid[3 * p + 2];

    const float sigma = r / 3.0f;
    const float half  = ceilf(2.0f * sigma);
    if (tid < 2 * H + 1) {
        float pos = (float)(tid - H);
        float v   = expf(-0.5f * (pos / sigma) * (pos / sigma));
        w[tid]    = (fabsf(pos) <= half) ? v : 0.0f;
    }
    __syncthreads();
    if (tid == 0) {
        float s = 0.0f;
        #pragma unroll
        for (int k = 0; k < 2 * H + 1; k++) s += w[k];
        s_wsum = s;
    }

    grid_barrier();   // image fully zeroed

    // ---------------- Phase B: phosphene scatter ----------------
    {
        const float cx = x - 1.0f, cy = y - 1.0f;   // 0-based center
        const float r2 = r * r;

        int oy0 = max(0,        (int)floorf(cy - r) - H);
        int oy1 = min(SIZE - 1, (int)ceilf (cy + r) + H);
        int ox0 = max(0,        (int)floorf(cx - r) - H);
        int ox1 = min(SIZE - 1, (int)ceilf (cx + r) + H);

        int cLo = max(0,        ox0 - H);
        int cHi = min(SIZE - 1, ox1 + H);

        int oh = oy1 - oy0 + 1;
        int ow = ox1 - ox0 + 1;
        int tw = cHi - cLo + 1;
        if (oh > MAX_OH) oh = MAX_OH;
        if (tw > MAX_TW) tw = MAX_TW;

        // vertical pass: analytic disk mask -> smem
        for (int idx = tid; idx < oh * tw; idx += NTHREADS) {
            int i   = idx / tw;
            int c   = idx - i * tw;
            int row = oy0 + i;
            int col = cLo + c;
            float dxc = (float)(col + 1) - x;       // coordinate is index+1
            float dx2 = dxc * dxc;
            float acc = 0.0f;
            #pragma unroll
            for (int dy = -H; dy <= H; dy++) {
                int   m   = refl(row + dy);
                float dyc = (float)(m + 1) - y;
                float inside = (dx2 + dyc * dyc <= r2) ? 1.0f : 0.0f;
                acc = fmaf(w[dy + H], inside, acc);
            }
            t[i][c] = acc;
        }
        __syncthreads();

        // horizontal pass + threshold + scatter
        const float wsum  = s_wsum;
        const float scale = bright / (wsum * wsum);
        for (int idx = tid; idx < oh * ow; idx += NTHREADS) {
            int i   = idx / ow;
            int j   = idx - i * ow;
            int col = ox0 + j;
            float acc = 0.0f;
            #pragma unroll
            for (int dx = -H; dx <= H; dx++) {
                int cc = refl(col + dx) - cLo;
                acc = fmaf(w[dx + H], t[i][cc], acc);
            }
            float val = acc * scale;
            if (val >= THRESH) {
                atomicAdd(&img[(oy0 + i) * SIZE + (ox0 + j)], val);
            }
        }
    }

    grid_barrier();   // all scatters complete

    // ---------------- Phase C: reduce max of clamped image (read-only) ----
    {
        int base = p * PX_PER_BLOCK + tid * 4;
        // bypass L1 (atomics from other SMs landed in L2)
        float4 v4 = __ldcg(reinterpret_cast<const float4*>(img + base));
        float v = fmaxf(fmaxf(fminf(v4.x, 1.f), fminf(v4.y, 1.f)),
                        fmaxf(fminf(v4.z, 1.f), fminf(v4.w, 1.f)));
        #pragma unroll
        for (int off = 16; off > 0; off >>= 1)
            v = fmaxf(v, __shfl_xor_sync(0xffffffffu, v, off));
        __shared__ float smax[8];
        int lane = tid & 31, wid = tid >> 5;
        if (lane == 0) smax[wid] = v;
        __syncthreads();
        if (wid == 0) {
            v = (lane < (NTHREADS >> 5)) ? smax[lane] : 0.0f;
            #pragma unroll
            for (int off = 4; off > 0; off >>= 1)
                v = fmaxf(v, __shfl_xor_sync(0xffffffffu, v, off));
            if (lane == 0) atomicMax(&g_max_bits, __float_as_int(v));
        }
    }

    grid_barrier();   // global max final

    // ---------------- Phase D: clamp + normalize, single write pass ------
    {
        float m = __int_as_float(__ldcg(&g_max_bits));
        int base = p * PX_PER_BLOCK + tid * 4;
        float4 v4 = __ldcg(reinterpret_cast<const float4*>(img + base));
        float4 o;
        o.x = fminf(v4.x, 1.f); o.y = fminf(v4.y, 1.f);
        o.z = fminf(v4.z, 1.f); o.w = fminf(v4.w, 1.f);
        if (m > 0.0f) { o.x /= m; o.y /= m; o.z /= m; o.w /= m; }
        *reinterpret_cast<float4*>(img + base) = o;
    }
}

extern "C" void kernel_launch(void* const* d_in, const int* in_sizes, int n_in,
                              void* d_out, int out_size) {
    const float* phos = (const float*)d_in[0];
    const float* grid = (const float*)d_in[1];
    if (n_in >= 2 && in_sizes[0] == 3 * N_PHOS && in_sizes[1] == N_PHOS) {
        const float* tmp = phos; phos = grid; grid = tmp;
    }
    float* img = (float*)d_out;

    k_fused<<<NBLOCKS, NTHREADS>>>(phos, grid, img);
}

// round 10
// speedup vs baseline: 1.1722x; 1.1722x over previous
#include <cuda_runtime.h>
#include <cuda_bf16.h>
#include <math.h>

#define SIZE   512
#define N_PHOS 256
#define H      10
#define THRESH 0.05f

#define MAX_OH 52        // disk span (<=31) + 2H + 1
#define MAX_TW 73        // MAX_OH + 2H (+1 pad)

#define NBLOCKS  N_PHOS
#define NTHREADS 256
#define PX_PER_BLOCK ((SIZE * SIZE) / NBLOCKS)   // 1024

__device__ int      g_max_bits  = 0;
__device__ unsigned g_bar_count = 0;
__device__ unsigned g_bar_gen   = 0;

static __device__ __forceinline__ int refl(int i) {
    if (i < 0)        i = -i;
    if (i > SIZE - 1) i = 2 * (SIZE - 1) - i;
    return i;
}

// Sense-reversing software grid barrier; all 256 blocks co-resident
// (2 blocks/SM cap x 148 SMs = 296 >= 256). State self-restores per use.
static __device__ __forceinline__ void grid_barrier() {
    __syncthreads();
    if (threadIdx.x == 0) {
        unsigned my_gen = *((volatile unsigned*)&g_bar_gen);
        __threadfence();
        unsigned arrived = atomicAdd(&g_bar_count, 1u);
        if (arrived == NBLOCKS - 1) {
            atomicExch(&g_bar_count, 0u);
            __threadfence();
            atomicExch(&g_bar_gen, my_gen + 1u);
        } else {
            while (*((volatile unsigned*)&g_bar_gen) == my_gen) { __nanosleep(32); }
        }
        __threadfence();
    }
    __syncthreads();
}

// Interval sum of taps dy in [a,b] (clamped to [-H,H]) from prefix weights.
// cw2[k] = w[0] + ... + w[k-1], cw2[0] = 0.
static __device__ __forceinline__ float ivsum(int a, int b, const float* __restrict__ cw2) {
    a = max(a, -H);
    b = min(b,  H);
    return (a <= b) ? (cw2[b + H + 1] - cw2[a + H]) : 0.0f;
}

__global__ __launch_bounds__(NTHREADS, 2) void k_fused(
    const float* __restrict__ phoscoding,
    const float* __restrict__ grid,
    float* __restrict__ img)
{
    const int p   = blockIdx.x;
    const int tid = threadIdx.x;

    __shared__ float w[2 * H + 1];
    __shared__ float cw2[2 * H + 2];          // prefix sums of w
    __shared__ short s_mLo[MAX_TW], s_mHi[MAX_TW];
    __shared__ float t[MAX_OH][MAX_TW];

    // ---------------- Phase A: zero image slice, reset max ----------------
    {
        int base = p * PX_PER_BLOCK + tid * 4;
        *reinterpret_cast<float4*>(img + base) = make_float4(0.f, 0.f, 0.f, 0.f);
        if (p == 0 && tid == 0) g_max_bits = 0;
    }

    // ---- phosphene params + tile geometry (overlaps zero propagation) ----
    const float bright = phoscoding[p];
    const float x = grid[3 * p + 0];
    const float y = grid[3 * p + 1];
    const float r = grid[3 * p + 2];

    const float sigma = r / 3.0f;
    const float half  = ceilf(2.0f * sigma);
    const float r2    = __fmul_rn(r, r);

    const float cx = x - 1.0f, cy = y - 1.0f;   // 0-based center

    const int oy0 = max(0,        (int)floorf(cy - r) - H);
    const int oy1 = min(SIZE - 1, (int)ceilf (cy + r) + H);
    const int ox0 = max(0,        (int)floorf(cx - r) - H);
    const int ox1 = min(SIZE - 1, (int)ceilf (cx + r) + H);

    const int cLo = max(0,        ox0 - H);
    const int cHi = min(SIZE - 1, ox1 + H);

    int oh = oy1 - oy0 + 1;          // <= 52
    int ow = ox1 - ox0 + 1;          // <= 52
    int tw = cHi - cLo + 1;          // <= 72
    if (oh > MAX_OH) oh = MAX_OH;
    if (tw > MAX_TW) tw = MAX_TW;

    // Blur weights (threads 0..20)
    if (tid < 2 * H + 1) {
        float pos = (float)(tid - H);
        float q   = pos / sigma;
        float v   = expf(-0.5f * (q * q));
        w[tid]    = (fabsf(pos) <= half) ? v : 0.0f;
    }

    // Per-column disk row-interval [mLo, mHi] (threads 0..tw-1).
    // Exact predicate matches reference rounding: rn(dx2 + rn(dyc*dyc)) <= rn(r*r).
    if (tid < tw) {
        int   col = cLo + tid;
        float dxc = (float)(col + 1) - x;
        float dx2 = __fmul_rn(dxc, dxc);
        int lo = 512, hi = -512;                 // empty sentinel
        if (dx2 <= r2) {
            float hy = sqrtf(fmaxf(r2 - dx2, 0.0f));
            lo = (int)ceilf (y - hy) - 1;
            hi = (int)floorf(y + hy) - 1;
            #pragma unroll
            for (int k = 0; k < 2; k++) {
                float d = (float)(lo) - y;       // m = lo-1 -> dyc = lo - y
                if (__fadd_rn(dx2, __fmul_rn(d, d)) <= r2) lo--;
            }
            #pragma unroll
            for (int k = 0; k < 2; k++) {
                float d = (float)(lo + 1) - y;   // m = lo
                if (!(__fadd_rn(dx2, __fmul_rn(d, d)) <= r2)) lo++;
            }
            #pragma unroll
            for (int k = 0; k < 2; k++) {
                float d = (float)(hi + 2) - y;   // m = hi+1
                if (__fadd_rn(dx2, __fmul_rn(d, d)) <= r2) hi++;
            }
            #pragma unroll
            for (int k = 0; k < 2; k++) {
                float d = (float)(hi + 1) - y;   // m = hi
                if (!(__fadd_rn(dx2, __fmul_rn(d, d)) <= r2)) hi--;
            }
            if (lo > hi) { lo = 512; hi = -512; }
        }
        s_mLo[tid] = (short)lo;
        s_mHi[tid] = (short)hi;
    }
    __syncthreads();
    if (tid == 0) {
        float s = 0.0f;
        cw2[0] = 0.0f;
        #pragma unroll
        for (int k = 0; k < 2 * H + 1; k++) { s += w[k]; cw2[k + 1] = s; }
    }

    grid_barrier();   // image zeroed everywhere; cw2/s_m* visible in-block

    // ---------------- Phase B: scatter ----------------
    {
        // Vertical blur of analytic disk mask via prefix-sum interval
        // differences (incl. both reflection intervals, O(1) per point).
        const int vtotal = oh << 7;                 // i = idx>>7, c = idx&127
        for (int idx = tid; idx < vtotal; idx += NTHREADS) {
            int c = idx & 127;
            if (c < tw) {
                int i   = idx >> 7;
                int row = oy0 + i;
                int lo  = s_mLo[c];
                int hi  = s_mHi[c];
                float v = ivsum(lo - row,        hi - row,        cw2)   // direct
                        + ivsum(-hi - row,       -lo - row,       cw2)   // bottom refl
                        + ivsum(1022 - hi - row, 1022 - lo - row, cw2);  // top refl
                t[i][c] = v;
            }
        }
        __syncthreads();

        // Horizontal 21-tap blur + threshold + atomic scatter
        const float wsum  = cw2[2 * H + 1];
        const float scale = bright / (wsum * wsum);
        const bool interior = (ox0 >= H) && (ox1 <= SIZE - 1 - H);
        const int htotal = oh << 6;                 // i = idx>>6, j = idx&63
        for (int idx = tid; idx < htotal; idx += NTHREADS) {
            int j = idx & 63;
            if (j < ow) {
                int i   = idx >> 6;
                int col = ox0 + j;
                float acc = 0.0f;
                if (interior) {
                    const float* trow = &t[i][col - cLo - H];
                    #pragma unroll
                    for (int k = 0; k < 2 * H + 1; k++)
                        acc = fmaf(w[k], trow[k], acc);
                } else {
                    #pragma unroll
                    for (int dx = -H; dx <= H; dx++) {
                        int cc = refl(col + dx) - cLo;
                        acc = fmaf(w[dx + H], t[i][cc], acc);
                    }
                }
                float val = acc * scale;
                if (val >= THRESH)
                    atomicAdd(&img[(oy0 + i) * SIZE + col], val);
            }
        }
    }

    grid_barrier();   // all scatters complete

    // ---------------- Phase C: max of clamped image (read-only) ----------
    {
        int base = p * PX_PER_BLOCK + tid * 4;
        float4 v4 = __ldcg(reinterpret_cast<const float4*>(img + base));
        float v = fmaxf(fmaxf(fminf(v4.x, 1.f), fminf(v4.y, 1.f)),
                        fmaxf(fminf(v4.z, 1.f), fminf(v4.w, 1.f)));
        #pragma unroll
        for (int off = 16; off > 0; off >>= 1)
            v = fmaxf(v, __shfl_xor_sync(0xffffffffu, v, off));
        __shared__ float smax[8];
        int lane = tid & 31, wid = tid >> 5;
        if (lane == 0) smax[wid] = v;
        __syncthreads();
        if (wid == 0) {
            v = (lane < (NTHREADS >> 5)) ? smax[lane] : 0.0f;
            #pragma unroll
            for (int off = 4; off > 0; off >>= 1)
                v = fmaxf(v, __shfl_xor_sync(0xffffffffu, v, off));
            if (lane == 0) atomicMax(&g_max_bits, __float_as_int(v));
        }
    }

    grid_barrier();   // global max final

    // ---------------- Phase D: clamp + normalize, single write ----------
    {
        float m = __int_as_float(__ldcg(&g_max_bits));
        int base = p * PX_PER_BLOCK + tid * 4;
        float4 v4 = __ldcg(reinterpret_cast<const float4*>(img + base));
        float4 o;
        o.x = fminf(v4.x, 1.f); o.y = fminf(v4.y, 1.f);
        o.z = fminf(v4.z, 1.f); o.w = fminf(v4.w, 1.f);
        if (m > 0.0f) { o.x /= m; o.y /= m; o.z /= m; o.w /= m; }
        *reinterpret_cast<float4*>(img + base) = o;
    }
}

extern "C" void kernel_launch(void* const* d_in, const int* in_sizes, int n_in,
                              void* d_out, int out_size) {
    const float* phos = (const float*)d_in[0];
    const float* grid = (const float*)d_in[1];
    if (n_in >= 2 && in_sizes[0] == 3 * N_PHOS && in_sizes[1] == N_PHOS) {
        const float* tmp = phos; phos = grid; grid = tmp;
    }
    float* img = (float*)d_out;

    k_fused<<<NBLOCKS, NTHREADS>>>(phos, grid, img);
}

// round 11
// speedup vs baseline: 1.1737x; 1.0013x over previous
#include <cuda_runtime.h>
#include <cuda_bf16.h>
#include <math.h>

#define SIZE   512
#define N_PHOS 256
#define H      10
#define THRESH 0.05f

#define MAX_OH 52        // disk span (<=31) + 2H + 1
#define MAX_TW 73        // MAX_OH + 2H (+1 pad)

#define NBLOCKS  N_PHOS
#define NTHREADS 256
#define PX_PER_BLOCK ((SIZE * SIZE) / NBLOCKS)   // 1024

__device__ int      g_max_bits  = 0;
__device__ unsigned g_bar_count = 0;
__device__ unsigned g_bar_gen   = 0;

static __device__ __forceinline__ int refl(int i) {
    if (i < 0)        i = -i;
    if (i > SIZE - 1) i = 2 * (SIZE - 1) - i;
    return i;
}

// Sense-reversing software grid barrier; all 256 blocks co-resident
// (2 blocks/SM cap x 148 SMs = 296 >= 256). State self-restores per use.
static __device__ __forceinline__ void grid_barrier() {
    __syncthreads();
    if (threadIdx.x == 0) {
        unsigned my_gen = *((volatile unsigned*)&g_bar_gen);
        __threadfence();
        unsigned arrived = atomicAdd(&g_bar_count, 1u);
        if (arrived == NBLOCKS - 1) {
            atomicExch(&g_bar_count, 0u);
            __threadfence();
            atomicExch(&g_bar_gen, my_gen + 1u);
        } else {
            while (*((volatile unsigned*)&g_bar_gen) == my_gen) { __nanosleep(32); }
        }
        __threadfence();
    }
    __syncthreads();
}

// Interval sum of taps dy in [a,b] (clamped to [-H,H]) from prefix weights.
// cw2[k] = w[0] + ... + w[k-1], cw2[0] = 0.
static __device__ __forceinline__ float ivsum(int a, int b, const float* __restrict__ cw2) {
    a = max(a, -H);
    b = min(b,  H);
    return (a <= b) ? (cw2[b + H + 1] - cw2[a + H]) : 0.0f;
}

__global__ __launch_bounds__(NTHREADS, 2) void k_fused(
    const float* __restrict__ phoscoding,
    const float* __restrict__ grid,
    float* __restrict__ img)
{
    const int p   = blockIdx.x;
    const int tid = threadIdx.x;

    __shared__ float w[2 * H + 1];
    __shared__ float cw2[2 * H + 2];          // prefix sums of w
    __shared__ short s_mLo[MAX_TW], s_mHi[MAX_TW];
    __shared__ float t[MAX_OH][MAX_TW];

    // ---------------- Phase A: zero image slice, reset max ----------------
    {
        int base = p * PX_PER_BLOCK + tid * 4;
        *reinterpret_cast<float4*>(img + base) = make_float4(0.f, 0.f, 0.f, 0.f);
        if (p == 0 && tid == 0) g_max_bits = 0;
    }

    // ---- phosphene params + tile geometry (overlaps zero propagation) ----
    const float bright = phoscoding[p];
    const float x = grid[3 * p + 0];
    const float y = grid[3 * p + 1];
    const float r = grid[3 * p + 2];

    const float sigma = r / 3.0f;
    const float half  = ceilf(2.0f * sigma);
    const float r2    = __fmul_rn(r, r);

    const float cx = x - 1.0f, cy = y - 1.0f;   // 0-based center

    const int oy0 = max(0,        (int)floorf(cy - r) - H);
    const int oy1 = min(SIZE - 1, (int)ceilf (cy + r) + H);
    const int ox0 = max(0,        (int)floorf(cx - r) - H);
    const int ox1 = min(SIZE - 1, (int)ceilf (cx + r) + H);

    const int cLo = max(0,        ox0 - H);
    const int cHi = min(SIZE - 1, ox1 + H);

    int oh = oy1 - oy0 + 1;          // <= 52
    int ow = ox1 - ox0 + 1;          // <= 52
    int tw = cHi - cLo + 1;          // <= 72
    if (oh > MAX_OH) oh = MAX_OH;
    if (tw > MAX_TW) tw = MAX_TW;

    // Blur weights (threads 0..20)
    if (tid < 2 * H + 1) {
        float pos = (float)(tid - H);
        float q   = pos / sigma;
        float v   = expf(-0.5f * (q * q));
        w[tid]    = (fabsf(pos) <= half) ? v : 0.0f;
    }

    // Per-column disk row-interval [mLo, mHi] (threads 0..tw-1).
    // Exact predicate matches reference rounding: rn(dx2 + rn(dyc*dyc)) <= rn(r*r).
    if (tid < tw) {
        int   col = cLo + tid;
        float dxc = (float)(col + 1) - x;
        float dx2 = __fmul_rn(dxc, dxc);
        int lo = 512, hi = -512;                 // empty sentinel
        if (dx2 <= r2) {
            float hy = sqrtf(fmaxf(r2 - dx2, 0.0f));
            lo = (int)ceilf (y - hy) - 1;
            hi = (int)floorf(y + hy) - 1;
            #pragma unroll
            for (int k = 0; k < 2; k++) {
                float d = (float)(lo) - y;       // m = lo-1 -> dyc = lo - y
                if (__fadd_rn(dx2, __fmul_rn(d, d)) <= r2) lo--;
            }
            #pragma unroll
            for (int k = 0; k < 2; k++) {
                float d = (float)(lo + 1) - y;   // m = lo
                if (!(__fadd_rn(dx2, __fmul_rn(d, d)) <= r2)) lo++;
            }
            #pragma unroll
            for (int k = 0; k < 2; k++) {
                float d = (float)(hi + 2) - y;   // m = hi+1
                if (__fadd_rn(dx2, __fmul_rn(d, d)) <= r2) hi++;
            }
            #pragma unroll
            for (int k = 0; k < 2; k++) {
                float d = (float)(hi + 1) - y;   // m = hi
                if (!(__fadd_rn(dx2, __fmul_rn(d, d)) <= r2)) hi--;
            }
            if (lo > hi) { lo = 512; hi = -512; }
        }
        s_mLo[tid] = (short)lo;
        s_mHi[tid] = (short)hi;
    }
    __syncthreads();
    if (tid == 0) {
        float s = 0.0f;
        cw2[0] = 0.0f;
        #pragma unroll
        for (int k = 0; k < 2 * H + 1; k++) { s += w[k]; cw2[k + 1] = s; }
    }

    grid_barrier();   // image zeroed everywhere; cw2/s_m* visible in-block

    // ---------------- Phase B: scatter ----------------
    {
        // Vertical blur of analytic disk mask via prefix-sum interval
        // differences (incl. both reflection intervals, O(1) per point).
        const int vtotal = oh << 7;                 // i = idx>>7, c = idx&127
        for (int idx = tid; idx < vtotal; idx += NTHREADS) {
            int c = idx & 127;
            if (c < tw) {
                int i   = idx >> 7;
                int row = oy0 + i;
                int lo  = s_mLo[c];
                int hi  = s_mHi[c];
                float v = ivsum(lo - row,        hi - row,        cw2)   // direct
                        + ivsum(-hi - row,       -lo - row,       cw2)   // bottom refl
                        + ivsum(1022 - hi - row, 1022 - lo - row, cw2);  // top refl
                t[i][c] = v;
            }
        }
        __syncthreads();

        // Horizontal 21-tap blur + threshold + atomic scatter
        const float wsum  = cw2[2 * H + 1];
        const float scale = bright / (wsum * wsum);
        const bool interior = (ox0 >= H) && (ox1 <= SIZE - 1 - H);
        const int htotal = oh << 6;                 // i = idx>>6, j = idx&63
        for (int idx = tid; idx < htotal; idx += NTHREADS) {
            int j = idx & 63;
            if (j < ow) {
                int i   = idx >> 6;
                int col = ox0 + j;
                float acc = 0.0f;
                if (interior) {
                    const float* trow = &t[i][col - cLo - H];
                    #pragma unroll
                    for (int k = 0; k < 2 * H + 1; k++)
                        acc = fmaf(w[k], trow[k], acc);
                } else {
                    #pragma unroll
                    for (int dx = -H; dx <= H; dx++) {
                        int cc = refl(col + dx) - cLo;
                        acc = fmaf(w[dx + H], t[i][cc], acc);
                    }
                }
                float val = acc * scale;
                if (val >= THRESH)
                    atomicAdd(&img[(oy0 + i) * SIZE + col], val);
            }
        }
    }

    grid_barrier();   // all scatters complete

    // ---------------- Phase C: max of clamped image (read-only) ----------
    {
        int base = p * PX_PER_BLOCK + tid * 4;
        float4 v4 = __ldcg(reinterpret_cast<const float4*>(img + base));
        float v = fmaxf(fmaxf(fminf(v4.x, 1.f), fminf(v4.y, 1.f)),
                        fmaxf(fminf(v4.z, 1.f), fminf(v4.w, 1.f)));
        #pragma unroll
        for (int off = 16; off > 0; off >>= 1)
            v = fmaxf(v, __shfl_xor_sync(0xffffffffu, v, off));
        __shared__ float smax[8];
        int lane = tid & 31, wid = tid >> 5;
        if (lane == 0) smax[wid] = v;
        __syncthreads();
        if (wid == 0) {
            v = (lane < (NTHREADS >> 5)) ? smax[lane] : 0.0f;
            #pragma unroll
            for (int off = 4; off > 0; off >>= 1)
                v = fmaxf(v, __shfl_xor_sync(0xffffffffu, v, off));
            if (lane == 0) atomicMax(&g_max_bits, __float_as_int(v));
        }
    }

    grid_barrier();   // global max final

    // ---------------- Phase D: clamp + normalize, single write ----------
    {
        float m = __int_as_float(__ldcg(&g_max_bits));
        int base = p * PX_PER_BLOCK + tid * 4;
        float4 v4 = __ldcg(reinterpret_cast<const float4*>(img + base));
        float4 o;
        o.x = fminf(v4.x, 1.f); o.y = fminf(v4.y, 1.f);
        o.z = fminf(v4.z, 1.f); o.w = fminf(v4.w, 1.f);
        if (m > 0.0f) { o.x /= m; o.y /= m; o.z /= m; o.w /= m; }
        *reinterpret_cast<float4*>(img + base) = o;
    }
}

extern "C" void kernel_launch(void* const* d_in, const int* in_sizes, int n_in,
                              void* d_out, int out_size) {
    const float* phos = (const float*)d_in[0];
    const float* grid = (const float*)d_in[1];
    if (n_in >= 2 && in_sizes[0] == 3 * N_PHOS && in_sizes[1] == N_PHOS) {
        const float* tmp = phos; phos = grid; grid = tmp;
    }
    float* img = (float*)d_out;

    k_fused<<<NBLOCKS, NTHREADS>>>(phos, grid, img);
}

// round 12
// speedup vs baseline: 1.2764x; 1.0875x over previous
#include <cuda_runtime.h>
#include <cuda_bf16.h>
#include <math.h>

#define SIZE   512
#define N_PHOS 256
#define H      10
#define THRESH 0.05f

#define MAX_OH 52        // disk span (<=31) + 2H + 1
#define MAX_TW 73        // MAX_OH + 2H (+1 pad)

#define NBLOCKS  N_PHOS
#define NTHREADS 256
#define PX_PER_BLOCK ((SIZE * SIZE) / NBLOCKS)   // 1024

// Self-restoring scratch accumulator: zero at module load; phase D re-zeros
// it every run, so it is zero at every kernel entry (replay-deterministic).
__device__ __align__(16) float g_scratch[SIZE * SIZE];

__device__ int      g_max_bits  = 0;
__device__ unsigned g_bar_count = 0;
__device__ unsigned g_bar_gen   = 0;

static __device__ __forceinline__ int refl(int i) {
    if (i < 0)        i = -i;
    if (i > SIZE - 1) i = 2 * (SIZE - 1) - i;
    return i;
}

// Sense-reversing software grid barrier; all 256 blocks co-resident
// (>=2 blocks/SM x 148 SMs >= 256). State self-restores per use.
static __device__ __forceinline__ void grid_barrier() {
    __syncthreads();
    if (threadIdx.x == 0) {
        unsigned my_gen = *((volatile unsigned*)&g_bar_gen);
        __threadfence();
        unsigned arrived = atomicAdd(&g_bar_count, 1u);
        if (arrived == NBLOCKS - 1) {
            atomicExch(&g_bar_count, 0u);
            __threadfence();
            atomicExch(&g_bar_gen, my_gen + 1u);
        } else {
            while (*((volatile unsigned*)&g_bar_gen) == my_gen) { __nanosleep(32); }
        }
        __threadfence();
    }
    __syncthreads();
}

// Interval sum of taps dy in [a,b] (clamped to [-H,H]) from prefix weights.
static __device__ __forceinline__ float ivsum(int a, int b, const float* __restrict__ cw2) {
    a = max(a, -H);
    b = min(b,  H);
    return (a <= b) ? (cw2[b + H + 1] - cw2[a + H]) : 0.0f;
}

__global__ __launch_bounds__(NTHREADS, 2) void k_fused(
    const float* __restrict__ phoscoding,
    const float* __restrict__ grid,
    float* __restrict__ img)
{
    const int p   = blockIdx.x;
    const int tid = threadIdx.x;

    __shared__ float w[2 * H + 1];
    __shared__ float cw2[2 * H + 2];          // prefix sums of w
    __shared__ short s_mLo[MAX_TW], s_mHi[MAX_TW];
    __shared__ float t[MAX_OH][MAX_TW];

    // Reset max scratch for this run (ordered vs. phase C by barrier 1).
    if (p == 0 && tid == 0) g_max_bits = 0;

    // ---- phosphene params + tile geometry ----
    const float bright = phoscoding[p];
    const float x = grid[3 * p + 0];
    const float y = grid[3 * p + 1];
    const float r = grid[3 * p + 2];

    const float sigma = r / 3.0f;
    const float half  = ceilf(2.0f * sigma);
    const float r2    = __fmul_rn(r, r);

    const float cx = x - 1.0f, cy = y - 1.0f;   // 0-based center

    const int oy0 = max(0,        (int)floorf(cy - r) - H);
    const int oy1 = min(SIZE - 1, (int)ceilf (cy + r) + H);
    const int ox0 = max(0,        (int)floorf(cx - r) - H);
    const int ox1 = min(SIZE - 1, (int)ceilf (cx + r) + H);

    const int cLo = max(0,        ox0 - H);
    const int cHi = min(SIZE - 1, ox1 + H);

    int oh = oy1 - oy0 + 1;          // <= 52
    int ow = ox1 - ox0 + 1;          // <= 52
    int tw = cHi - cLo + 1;          // <= 72
    if (oh > MAX_OH) oh = MAX_OH;
    if (tw > MAX_TW) tw = MAX_TW;

    // Blur weights (threads 0..20)
    if (tid < 2 * H + 1) {
        float pos = (float)(tid - H);
        float q   = pos / sigma;
        float v   = expf(-0.5f * (q * q));
        w[tid]    = (fabsf(pos) <= half) ? v : 0.0f;
    }

    // Per-column disk row-interval [mLo, mHi] (threads 0..tw-1).
    // Exact predicate matches reference rounding: rn(dx2 + rn(dyc*dyc)) <= rn(r*r).
    if (tid < tw) {
        int   col = cLo + tid;
        float dxc = (float)(col + 1) - x;
        float dx2 = __fmul_rn(dxc, dxc);
        int lo = 512, hi = -512;                 // empty sentinel
        if (dx2 <= r2) {
            float hy = sqrtf(fmaxf(r2 - dx2, 0.0f));
            lo = (int)ceilf (y - hy) - 1;
            hi = (int)floorf(y + hy) - 1;
            #pragma unroll
            for (int k = 0; k < 2; k++) {
                float d = (float)(lo) - y;
                if (__fadd_rn(dx2, __fmul_rn(d, d)) <= r2) lo--;
            }
            #pragma unroll
            for (int k = 0; k < 2; k++) {
                float d = (float)(lo + 1) - y;
                if (!(__fadd_rn(dx2, __fmul_rn(d, d)) <= r2)) lo++;
            }
            #pragma unroll
            for (int k = 0; k < 2; k++) {
                float d = (float)(hi + 2) - y;
                if (__fadd_rn(dx2, __fmul_rn(d, d)) <= r2) hi++;
            }
            #pragma unroll
            for (int k = 0; k < 2; k++) {
                float d = (float)(hi + 1) - y;
                if (!(__fadd_rn(dx2, __fmul_rn(d, d)) <= r2)) hi--;
            }
            if (lo > hi) { lo = 512; hi = -512; }
        }
        s_mLo[tid] = (short)lo;
        s_mHi[tid] = (short)hi;
    }
    __syncthreads();
    if (tid == 0) {
        float s = 0.0f;
        cw2[0] = 0.0f;
        #pragma unroll
        for (int k = 0; k < 2 * H + 1; k++) { s += w[k]; cw2[k + 1] = s; }
    }
    __syncthreads();

    // ---------------- Phase B: scatter into g_scratch ----------------
    {
        // Vertical blur of analytic disk mask via prefix-sum interval
        // differences (incl. both reflection intervals, O(1) per point).
        const int vtotal = oh << 7;                 // i = idx>>7, c = idx&127
        for (int idx = tid; idx < vtotal; idx += NTHREADS) {
            int c = idx & 127;
            if (c < tw) {
                int i   = idx >> 7;
                int row = oy0 + i;
                int lo  = s_mLo[c];
                int hi  = s_mHi[c];
                float v = ivsum(lo - row,        hi - row,        cw2)   // direct
                        + ivsum(-hi - row,       -lo - row,       cw2)   // bottom refl
                        + ivsum(1022 - hi - row, 1022 - lo - row, cw2);  // top refl
                t[i][c] = v;
            }
        }
        __syncthreads();

        // Horizontal 21-tap blur + threshold + atomic scatter
        const float wsum  = cw2[2 * H + 1];
        const float scale = bright / (wsum * wsum);
        const bool interior = (ox0 >= H) && (ox1 <= SIZE - 1 - H);
        const int htotal = oh << 6;                 // i = idx>>6, j = idx&63
        for (int idx = tid; idx < htotal; idx += NTHREADS) {
            int j = idx & 63;
            if (j < ow) {
                int i   = idx >> 6;
                int col = ox0 + j;
                float acc = 0.0f;
                if (interior) {
                    const float* trow = &t[i][col - cLo - H];
                    #pragma unroll
                    for (int k = 0; k < 2 * H + 1; k++)
                        acc = fmaf(w[k], trow[k], acc);
                } else {
                    #pragma unroll
                    for (int dx = -H; dx <= H; dx++) {
                        int cc = refl(col + dx) - cLo;
                        acc = fmaf(w[dx + H], t[i][cc], acc);
                    }
                }
                float val = acc * scale;
                if (val >= THRESH)
                    atomicAdd(&g_scratch[(oy0 + i) * SIZE + col], val);
            }
        }
    }

    grid_barrier();   // all scatters complete; g_max_bits reset visible

    // ------- Phase C: load + clamp (keep in regs), reduce global max -------
    const int base = p * PX_PER_BLOCK + tid * 4;
    float4 v4 = __ldcg(reinterpret_cast<const float4*>(g_scratch + base));
    v4.x = fminf(v4.x, 1.f); v4.y = fminf(v4.y, 1.f);
    v4.z = fminf(v4.z, 1.f); v4.w = fminf(v4.w, 1.f);
    {
        float v = fmaxf(fmaxf(v4.x, v4.y), fmaxf(v4.z, v4.w));
        #pragma unroll
        for (int off = 16; off > 0; off >>= 1)
            v = fmaxf(v, __shfl_xor_sync(0xffffffffu, v, off));
        __shared__ float smax[8];
        int lane = tid & 31, wid = tid >> 5;
        if (lane == 0) smax[wid] = v;
        __syncthreads();
        if (wid == 0) {
            v = (lane < (NTHREADS >> 5)) ? smax[lane] : 0.0f;
            #pragma unroll
            for (int off = 4; off > 0; off >>= 1)
                v = fmaxf(v, __shfl_xor_sync(0xffffffffu, v, off));
            if (lane == 0) atomicMax(&g_max_bits, __float_as_int(v));
        }
    }

    grid_barrier();   // global max final

    // ---- Phase D: normalize regs -> d_out; re-zero scratch for next run ----
    {
        float m = __int_as_float(__ldcg(&g_max_bits));
        if (m > 0.0f) {
            float inv = 1.0f / m;   // note: ref uses /m; use div for exactness
            v4.x /= m; v4.y /= m; v4.z /= m; v4.w /= m;
            (void)inv;
        }
        *reinterpret_cast<float4*>(img + base) = v4;
        *reinterpret_cast<float4*>(g_scratch + base) = make_float4(0.f, 0.f, 0.f, 0.f);
    }
}

extern "C" void kernel_launch(void* const* d_in, const int* in_sizes, int n_in,
                              void* d_out, int out_size) {
    const float* phos = (const float*)d_in[0];
    const float* grid = (const float*)d_in[1];
    if (n_in >= 2 && in_sizes[0] == 3 * N_PHOS && in_sizes[1] == N_PHOS) {
        const float* tmp = phos; phos = grid; grid = tmp;
    }
    float* img = (float*)d_out;

    k_fused<<<NBLOCKS, NTHREADS>>>(phos, grid, img);
}

// round 13
// speedup vs baseline: 1.4031x; 1.0992x over previous
#include <cuda_runtime.h>
#include <cuda_bf16.h>
#include <math.h>

#define SIZE   512
#define N_PHOS 256
#define H      10
#define THRESH 0.05f

#define MAX_OH 52        // disk span (<=31) + 2H + 1
#define MAX_TW 73        // MAX_OH + 2H (+1 pad)

#define NBLOCKS  128                 // one block per SM; 2 phosphenes each
#define NTHREADS 512
#define PX_PER_BLOCK ((SIZE * SIZE) / NBLOCKS)   // 2048 -> one float4 / thread

// Self-restoring scratch accumulator: zero at module load; phase D re-zeros
// it every run, so it is zero at every kernel entry (replay-deterministic).
__device__ __align__(16) float g_scratch[SIZE * SIZE];

__device__ int      g_max_bits  = 0;
__device__ unsigned g_bar_count = 0;
__device__ unsigned g_bar_gen   = 0;

static __device__ __forceinline__ int refl(int i) {
    if (i < 0)        i = -i;
    if (i > SIZE - 1) i = 2 * (SIZE - 1) - i;
    return i;
}

// Sense-reversing software grid barrier; all 128 blocks co-resident
// (grid 128 < 148 SMs, 1 block/SM guaranteed). Self-restoring state.
static __device__ __forceinline__ void grid_barrier() {
    __syncthreads();
    if (threadIdx.x == 0) {
        unsigned my_gen = *((volatile unsigned*)&g_bar_gen);
        __threadfence();
        unsigned arrived = atomicAdd(&g_bar_count, 1u);
        if (arrived == NBLOCKS - 1) {
            atomicExch(&g_bar_count, 0u);
            __threadfence();
            atomicExch(&g_bar_gen, my_gen + 1u);
        } else {
            while (*((volatile unsigned*)&g_bar_gen) == my_gen) { __nanosleep(32); }
        }
        __threadfence();
    }
    __syncthreads();
}

// Interval sum of taps dy in [a,b] (clamped to [-H,H]) from prefix weights.
static __device__ __forceinline__ float ivsum(int a, int b, const float* __restrict__ cw2) {
    a = max(a, -H);
    b = min(b,  H);
    return (a <= b) ? (cw2[b + H + 1] - cw2[a + H]) : 0.0f;
}

__global__ __launch_bounds__(NTHREADS, 1) void k_fused(
    const float* __restrict__ phoscoding,
    const float* __restrict__ grid,
    float* __restrict__ img)
{
    const int tid  = threadIdx.x;
    const int sub  = tid >> 8;                    // 0/1: which phosphene half
    const int l    = tid & 255;                   // lane within half-block
    const int p    = (blockIdx.x << 1) + sub;     // phosphene id

    __shared__ float w[2][2 * H + 1];
    __shared__ float cw2[2][2 * H + 2];
    __shared__ short s_mLo[2][MAX_TW], s_mHi[2][MAX_TW];
    __shared__ float t[2][MAX_OH][MAX_TW];

    if (blockIdx.x == 0 && tid == 0) g_max_bits = 0;

    // ---- phosphene params + tile geometry ----
    const float bright = phoscoding[p];
    const float x = grid[3 * p + 0];
    const float y = grid[3 * p + 1];
    const float r = grid[3 * p + 2];

    const float sigma = r / 3.0f;
    const float half  = ceilf(2.0f * sigma);
    const float r2    = __fmul_rn(r, r);

    const float cx = x - 1.0f, cy = y - 1.0f;   // 0-based center

    const int oy0 = max(0,        (int)floorf(cy - r) - H);
    const int oy1 = min(SIZE - 1, (int)ceilf (cy + r) + H);
    const int ox0 = max(0,        (int)floorf(cx - r) - H);
    const int ox1 = min(SIZE - 1, (int)ceilf (cx + r) + H);

    const int cLo = max(0,        ox0 - H);
    const int cHi = min(SIZE - 1, ox1 + H);

    int oh = oy1 - oy0 + 1;          // <= 52
    int ow = ox1 - ox0 + 1;          // <= 52
    int tw = cHi - cLo + 1;          // <= 72
    if (oh > MAX_OH) oh = MAX_OH;
    if (tw > MAX_TW) tw = MAX_TW;

    // Blur weights (lanes 0..20 of each half)
    if (l < 2 * H + 1) {
        float pos = (float)(l - H);
        float q   = pos / sigma;
        float v   = expf(-0.5f * (q * q));
        w[sub][l] = (fabsf(pos) <= half) ? v : 0.0f;
    }

    // Per-column disk row-interval [mLo, mHi] (lanes 0..tw-1).
    // Exact predicate matches reference rounding: rn(dx2 + rn(dyc*dyc)) <= rn(r*r).
    if (l < tw) {
        int   col = cLo + l;
        float dxc = (float)(col + 1) - x;
        float dx2 = __fmul_rn(dxc, dxc);
        int lo = 512, hi = -512;                 // empty sentinel
        if (dx2 <= r2) {
            float hy = sqrtf(fmaxf(r2 - dx2, 0.0f));
            lo = (int)ceilf (y - hy) - 1;
            hi = (int)floorf(y + hy) - 1;
            #pragma unroll
            for (int k = 0; k < 2; k++) {
                float d = (float)(lo) - y;
                if (__fadd_rn(dx2, __fmul_rn(d, d)) <= r2) lo--;
            }
            #pragma unroll
            for (int k = 0; k < 2; k++) {
                float d = (float)(lo + 1) - y;
                if (!(__fadd_rn(dx2, __fmul_rn(d, d)) <= r2)) lo++;
            }
            #pragma unroll
            for (int k = 0; k < 2; k++) {
                float d = (float)(hi + 2) - y;
                if (__fadd_rn(dx2, __fmul_rn(d, d)) <= r2) hi++;
            }
            #pragma unroll
            for (int k = 0; k < 2; k++) {
                float d = (float)(hi + 1) - y;
                if (!(__fadd_rn(dx2, __fmul_rn(d, d)) <= r2)) hi--;
            }
            if (lo > hi) { lo = 512; hi = -512; }
        }
        s_mLo[sub][l] = (short)lo;
        s_mHi[sub][l] = (short)hi;
    }
    __syncthreads();
    if (l == 0) {
        float s = 0.0f;
        cw2[sub][0] = 0.0f;
        #pragma unroll
        for (int k = 0; k < 2 * H + 1; k++) { s += w[sub][k]; cw2[sub][k + 1] = s; }
    }
    __syncthreads();

    // ---------------- Phase B: scatter into g_scratch ----------------
    {
        const float* cwp = cw2[sub];
        // Vertical blur via prefix-sum interval differences (O(1)/point,
        // incl. both reflection intervals).
        const int vtotal = oh << 7;                 // i = idx>>7, c = idx&127
        for (int idx = l; idx < vtotal; idx += 256) {
            int c = idx & 127;
            if (c < tw) {
                int i   = idx >> 7;
                int row = oy0 + i;
                int lo  = s_mLo[sub][c];
                int hi  = s_mHi[sub][c];
                float v = ivsum(lo - row,        hi - row,        cwp)   // direct
                        + ivsum(-hi - row,       -lo - row,       cwp)   // bottom refl
                        + ivsum(1022 - hi - row, 1022 - lo - row, cwp);  // top refl
                t[sub][i][c] = v;
            }
        }
        __syncthreads();

        // Horizontal 21-tap blur + threshold + atomic scatter
        const float wsum  = cwp[2 * H + 1];
        const float scale = bright / (wsum * wsum);
        const bool interior = (ox0 >= H) && (ox1 <= SIZE - 1 - H);
        const int htotal = oh << 6;                 // i = idx>>6, j = idx&63
        for (int idx = l; idx < htotal; idx += 256) {
            int j = idx & 63;
            if (j < ow) {
                int i   = idx >> 6;
                int col = ox0 + j;
                float acc = 0.0f;
                if (interior) {
                    const float* trow = &t[sub][i][col - cLo - H];
                    #pragma unroll
                    for (int k = 0; k < 2 * H + 1; k++)
                        acc = fmaf(w[sub][k], trow[k], acc);
                } else {
                    #pragma unroll
                    for (int dx = -H; dx <= H; dx++) {
                        int cc = refl(col + dx) - cLo;
                        acc = fmaf(w[sub][dx + H], t[sub][i][cc], acc);
                    }
                }
                float val = acc * scale;
                if (val >= THRESH)
                    atomicAdd(&g_scratch[(oy0 + i) * SIZE + col], val);
            }
        }
    }

    grid_barrier();   // all scatters complete; g_max_bits reset visible

    // ------- Phase C: load + clamp (keep in regs), reduce global max -------
    const int base = blockIdx.x * PX_PER_BLOCK + tid * 4;
    float4 v4 = __ldcg(reinterpret_cast<const float4*>(g_scratch + base));
    v4.x = fminf(v4.x, 1.f); v4.y = fminf(v4.y, 1.f);
    v4.z = fminf(v4.z, 1.f); v4.w = fminf(v4.w, 1.f);
    {
        float v = fmaxf(fmaxf(v4.x, v4.y), fmaxf(v4.z, v4.w));
        #pragma unroll
        for (int off = 16; off > 0; off >>= 1)
            v = fmaxf(v, __shfl_xor_sync(0xffffffffu, v, off));
        __shared__ float smax[16];
        int lane = tid & 31, wid = tid >> 5;
        if (lane == 0) smax[wid] = v;
        __syncthreads();
        if (wid == 0) {
            v = (lane < (NTHREADS >> 5)) ? smax[lane] : 0.0f;
            #pragma unroll
            for (int off = 8; off > 0; off >>= 1)
                v = fmaxf(v, __shfl_xor_sync(0xffffffffu, v, off));
            if (lane == 0) atomicMax(&g_max_bits, __float_as_int(v));
        }
    }

    grid_barrier();   // global max final

    // ---- Phase D: normalize regs -> d_out; re-zero scratch for next run ----
    {
        float m = __int_as_float(__ldcg(&g_max_bits));
        if (m > 0.0f) { v4.x /= m; v4.y /= m; v4.z /= m; v4.w /= m; }
        *reinterpret_cast<float4*>(img + base) = v4;
        *reinterpret_cast<float4*>(g_scratch + base) = make_float4(0.f, 0.f, 0.f, 0.f);
    }
}

extern "C" void kernel_launch(void* const* d_in, const int* in_sizes, int n_in,
                              void* d_out, int out_size) {
    const float* phos = (const float*)d_in[0];
    const float* grid = (const float*)d_in[1];
    if (n_in >= 2 && in_sizes[0] == 3 * N_PHOS && in_sizes[1] == N_PHOS) {
        const float* tmp = phos; phos = grid; grid = tmp;
    }
    float* img = (float*)d_out;

    k_fused<<<NBLOCKS, NTHREADS>>>(phos, grid, img);
}